// round 1
// baseline (speedup 1.0000x reference)
#include <cuda_runtime.h>

#define NBINS 5
#define RED_BLOCKS 1184   /* 148 SMs * 8 */
#define APPLY_BLOCKS 2368 /* 148 SMs * 16 */
#define NT 256

// ---------------- device scratch (no allocation allowed) ----------------
__device__ unsigned int       g_min_u;
__device__ unsigned int       g_max_u;
__device__ unsigned long long g_counts[NBINS];
__device__ float              g_dmin, g_width;
// table layout:
//  [0..7]   (slope, base) pairs for the 4 interp segments of index(d)
//  [8..17]  (theta_p, velo_p) pairs for the 5 frame points
//  [18] ct  [19] st  [20] invw  [21] c0 (= -dmin/width - 0.5)
__device__ float              g_tbl[24];

// ---------------- ordered-uint encoding for float atomicMin/Max ----------------
__device__ __forceinline__ unsigned int fou(float f) {
    unsigned int u = __float_as_uint(f);
    return (u & 0x80000000u) ? ~u : (u | 0x80000000u);
}
__device__ __forceinline__ float ouf(unsigned int u) {
    return __uint_as_float((u & 0x80000000u) ? (u & 0x7fffffffu) : ~u);
}

// ---------------- kernel 0: reset scratch (graph-replay deterministic) ----------------
__global__ void k_init() {
    if (threadIdx.x == 0) { g_min_u = 0xFFFFFFFFu; g_max_u = 0u; }
    if (threadIdx.x < NBINS) g_counts[threadIdx.x] = 0ull;
}

// ---------------- kernel 1: min/max of raw data ----------------
__global__ void k_minmax(const float4* __restrict__ x, int n4, const float* __restrict__ xs, int n) {
    float mn =  3.402823466e38f;
    float mx = -3.402823466e38f;
    const int stride = gridDim.x * blockDim.x;
    for (int i = blockIdx.x * blockDim.x + threadIdx.x; i < n4; i += stride) {
        float4 v = x[i];
        mn = fminf(mn, fminf(fminf(v.x, v.y), fminf(v.z, v.w)));
        mx = fmaxf(mx, fmaxf(fmaxf(v.x, v.y), fmaxf(v.z, v.w)));
    }
    // scalar tail
    for (int i = (n4 << 2) + blockIdx.x * blockDim.x + threadIdx.x; i < n; i += stride) {
        float v = xs[i];
        mn = fminf(mn, v); mx = fmaxf(mx, v);
    }
    #pragma unroll
    for (int o = 16; o > 0; o >>= 1) {
        mn = fminf(mn, __shfl_xor_sync(0xffffffffu, mn, o));
        mx = fmaxf(mx, __shfl_xor_sync(0xffffffffu, mx, o));
    }
    __shared__ float smn[NT / 32], smx[NT / 32];
    int w = threadIdx.x >> 5;
    if ((threadIdx.x & 31) == 0) { smn[w] = mn; smx[w] = mx; }
    __syncthreads();
    if (threadIdx.x == 0) {
        #pragma unroll
        for (int i = 1; i < NT / 32; i++) { mn = fminf(mn, smn[i]); mx = fmaxf(mx, smx[i]); }
        atomicMin(&g_min_u, fou(mn));
        atomicMax(&g_max_u, fou(mx));
    }
}

// ---------------- kernel 2: dmin/width from min/max and channel scalar ----------------
__global__ void k_prep1(const float* __restrict__ ct_p) {
    float mn = ouf(g_min_u), mx = ouf(g_max_u);
    float ct = ct_p[0];
    float a = ct * mn, b = ct * mx;                 // exact fp32 products; monotone map
    float dmn = fminf(a, b) - 0.1f;
    float dmx = fmaxf(a, b) + 0.1f;
    g_dmin  = dmn;
    g_width = (dmx - dmn) / (float)NBINS;
}

// ---------------- kernel 3: 5-bin histogram (exact integer counts) ----------------
__global__ void k_hist(const float4* __restrict__ x, int n4,
                       const float* __restrict__ xs, int n,
                       const float* __restrict__ ct_p) {
    const float ct   = ct_p[0];
    const float dmin = g_dmin;
    const float wdt  = g_width;
    unsigned int c0 = 0, c1 = 0, c2 = 0, c3 = 0, c4 = 0;
    const int stride = gridDim.x * blockDim.x;
    for (int i = blockIdx.x * blockDim.x + threadIdx.x; i < n4; i += stride) {
        float4 v = x[i];
        float e[4] = { v.x, v.y, v.z, v.w };
        #pragma unroll
        for (int k = 0; k < 4; k++) {
            float d = e[k] * ct;
            float q = (d - dmin) / wdt;             // match reference's division
            int b = (int)floorf(q);
            b = min(max(b, 0), NBINS - 1);
            c0 += (b == 0); c1 += (b == 1); c2 += (b == 2); c3 += (b == 3); c4 += (b == 4);
        }
    }
    for (int i = (n4 << 2) + blockIdx.x * blockDim.x + threadIdx.x; i < n; i += stride) {
        float d = xs[i] * ct;
        float q = (d - dmin) / wdt;
        int b = (int)floorf(q);
        b = min(max(b, 0), NBINS - 1);
        c0 += (b == 0); c1 += (b == 1); c2 += (b == 2); c3 += (b == 3); c4 += (b == 4);
    }
    c0 = __reduce_add_sync(0xffffffffu, c0);
    c1 = __reduce_add_sync(0xffffffffu, c1);
    c2 = __reduce_add_sync(0xffffffffu, c2);
    c3 = __reduce_add_sync(0xffffffffu, c3);
    c4 = __reduce_add_sync(0xffffffffu, c4);
    __shared__ unsigned long long sc[NBINS];
    if (threadIdx.x < NBINS) sc[threadIdx.x] = 0ull;
    __syncthreads();
    if ((threadIdx.x & 31) == 0) {
        atomicAdd(&sc[0], (unsigned long long)c0);
        atomicAdd(&sc[1], (unsigned long long)c1);
        atomicAdd(&sc[2], (unsigned long long)c2);
        atomicAdd(&sc[3], (unsigned long long)c3);
        atomicAdd(&sc[4], (unsigned long long)c4);
    }
    __syncthreads();
    if (threadIdx.x < NBINS) atomicAdd(&g_counts[threadIdx.x], sc[threadIdx.x]);
}

// ---------------- kernel 4: scalar table construction ----------------
__global__ void k_prep2(const float* __restrict__ params,
                        const float* __restrict__ ct_p,
                        const float* __restrict__ st_p) {
    if (threadIdx.x != 0 || blockIdx.x != 0) return;
    const float dmin = g_dmin, wdt = g_width;

    // emulate fp32 +=1.0 accumulation: saturates exactly at 2^24
    float cf[NBINS];
    #pragma unroll
    for (int i = 0; i < NBINS; i++) {
        unsigned long long c = g_counts[i];
        if (c > 16777216ull) c = 16777216ull;
        cf[i] = (float)c;
    }
    float s = cf[0] + cf[1] + cf[2] + cf[3] + cf[4];       // left-to-right fp32
    float accum[NBINS];
    float run = 0.0f;
    #pragma unroll
    for (int i = 0; i < NBINS; i++) {
        float prob = cf[i] / s;
        run += prob;
        accum[i] = run * (float)NBINS;
    }
    float edges[NBINS + 1], grid[NBINS];
    #pragma unroll
    for (int i = 0; i <= NBINS; i++) edges[i] = dmin + wdt * (float)i;
    #pragma unroll
    for (int i = 0; i < NBINS; i++) grid[i] = 0.5f * (edges[i + 1] + edges[i]);

    // per-segment slope/base for index(d) = interp1d(grid, accum, d)
    #pragma unroll
    for (int i = 0; i < NBINS - 1; i++) {
        float den = grid[i + 1] - grid[i];
        if (den == 0.0f) den = 1.0f;
        float slope = (accum[i + 1] - accum[i]) / den;
        g_tbl[2 * i]     = slope;
        g_tbl[2 * i + 1] = accum[i] - slope * grid[i];
    }
    // frame = interp1d(accum, grid, arange(P))
    float frame[NBINS];
    #pragma unroll
    for (int q = 0; q < NBINS; q++) {
        float xq = (float)q;
        int ss = 0;
        #pragma unroll
        for (int j = 0; j < NBINS; j++) ss += (accum[j] < xq);
        int idx = min(max(ss - 1, 0), NBINS - 2);
        float den = accum[idx + 1] - accum[idx];
        if (den == 0.0f) den = 1.0f;
        frame[q] = grid[idx] + (grid[idx + 1] - grid[idx]) / den * (xq - accum[idx]);
    }
    #pragma unroll
    for (int q = 0; q < NBINS; q++) {
        g_tbl[8 + 2 * q] = frame[q] + 0.001f * params[q];          // theta row
        g_tbl[9 + 2 * q] = frame[q] + 0.001f * params[NBINS + q];  // velocity row
    }
    g_tbl[18] = ct_p[0];
    g_tbl[19] = st_p[0];
    g_tbl[20] = 1.0f / wdt;
    g_tbl[21] = -dmin / wdt - 0.5f;
}

// ---------------- kernel 5: elementwise apply ----------------
__device__ __forceinline__ float apply_one(float xv, const float2* sb, const float2* tv,
                                           float ct, float st, float invw, float c0) {
    float d = xv * ct;
    // uniform grid centers -> segment index via one fma (continuous interp => boundary-safe)
    float t = fmaf(d, invw, c0);
    int idx = min(max((int)floorf(t), 0), NBINS - 2);
    float2 s = sb[idx];
    float index = fmaf(s.x, d, s.y);
    float bf = floorf(index);
    float pos = index - bf;
    int bi = (int)bf;
    int b = min(max(bi, 0), NBINS - 1);
    int e = min(max(bi + 1, 0), NBINS - 1);
    float2 B = tv[b];
    float2 E = tv[e];
    float th = fmaf(E.x - B.x, pos, B.x);
    float ve = fmaf(E.y - B.y, pos, B.y);
    float sn, cs;
    __sincosf(th, &sn, &cs);
    return fmaf(d, fmaf(ve, sn, 1.0f), ve * cs) * st;
}

__global__ void k_apply(const float4* __restrict__ x, float4* __restrict__ o, int n4,
                        const float* __restrict__ xs, float* __restrict__ os, int n) {
    __shared__ __align__(8) float tbl[24];
    if (threadIdx.x < 24) tbl[threadIdx.x] = g_tbl[threadIdx.x];
    __syncthreads();
    const float2* sb = (const float2*)tbl;         // 4 pairs
    const float2* tv = (const float2*)(tbl + 8);   // 5 pairs
    const float ct = tbl[18], st = tbl[19], invw = tbl[20], c0 = tbl[21];
    const int stride = gridDim.x * blockDim.x;
    for (int i = blockIdx.x * blockDim.x + threadIdx.x; i < n4; i += stride) {
        float4 v = x[i];
        float4 r;
        r.x = apply_one(v.x, sb, tv, ct, st, invw, c0);
        r.y = apply_one(v.y, sb, tv, ct, st, invw, c0);
        r.z = apply_one(v.z, sb, tv, ct, st, invw, c0);
        r.w = apply_one(v.w, sb, tv, ct, st, invw, c0);
        o[i] = r;
    }
    for (int i = (n4 << 2) + blockIdx.x * blockDim.x + threadIdx.x; i < n; i += stride)
        os[i] = apply_one(xs[i], sb, tv, ct, st, invw, c0);
}

// ---------------- launch ----------------
extern "C" void kernel_launch(void* const* d_in, const int* in_sizes, int n_in,
                              void* d_out, int out_size) {
    const float* data   = (const float*)d_in[0];
    const float* params = (const float*)d_in[1];
    const float* ct     = (const float*)d_in[2];
    const float* st     = (const float*)d_in[3];
    float* out = (float*)d_out;
    int n  = in_sizes[0];
    int n4 = n >> 2;

    k_init<<<1, 32>>>();
    k_minmax<<<RED_BLOCKS, NT>>>((const float4*)data, n4, data, n);
    k_prep1<<<1, 1>>>(ct);
    k_hist<<<RED_BLOCKS, NT>>>((const float4*)data, n4, data, n, ct);
    k_prep2<<<1, 1>>>(params, ct, st);
    k_apply<<<APPLY_BLOCKS, NT>>>((const float4*)data, (float4*)out, n4, data, out, n);
}

// round 2
// speedup vs baseline: 1.2459x; 1.2459x over previous
#include <cuda_runtime.h>

#define NBINS 5
#define NT   256
#define UN   4
#define GRID 2048   /* GRID*NT*UN = 2^21 float4 -> exactly 4 sweeps of n4 = 2^23 */

// ---------------- device scratch (no allocation allowed) ----------------
__device__ unsigned int g_min_u;
__device__ unsigned int g_max_u;
__device__ unsigned int g_s[4];       // s_k = count of q >= k, k=1..4
__device__ float        g_dmin, g_width, g_histA, g_histB;
// table layout (36 floats):
//  [0..7]   (slopeA_i = slope_i*ct, base_i) for the 4 index(d) segments
//  [8..31]  6 x float4: (thSlope, thInt, veSlope, veInt) keyed by clamp(floor(index)+1,0,5)
//  [32] At = ct/width   [33] c0 = -dmin/width - 0.5   [34] stct = st*ct   [35] st
__device__ float        g_tbl[36];

// ---------------- ordered-uint encoding for float atomicMin/Max ----------------
__device__ __forceinline__ unsigned int fou(float f) {
    unsigned int u = __float_as_uint(f);
    return (u & 0x80000000u) ? ~u : (u | 0x80000000u);
}
__device__ __forceinline__ float ouf(unsigned int u) {
    return __uint_as_float((u & 0x80000000u) ? (u & 0x7fffffffu) : ~u);
}

// ---------------- kernel 0: reset scratch (graph-replay deterministic) ----------------
__global__ void k_init() {
    if (threadIdx.x == 0) { g_min_u = 0xFFFFFFFFu; g_max_u = 0u; }
    if (threadIdx.x < 4) g_s[threadIdx.x] = 0u;
}

// ---------------- kernel 1: min/max of raw data ----------------
__global__ void k_minmax(const float4* __restrict__ x, int n4, const float* __restrict__ xs, int n) {
    float mn =  3.402823466e38f;
    float mx = -3.402823466e38f;
    int i = blockIdx.x * (NT * UN) + threadIdx.x;
    const int step = GRID * NT * UN;
    for (; i < n4; i += step) {
        #pragma unroll
        for (int k = 0; k < UN; k++) {
            int j = i + k * NT;
            if (j < n4) {
                float4 v = x[j];
                mn = fminf(mn, fminf(fminf(v.x, v.y), fminf(v.z, v.w)));
                mx = fmaxf(mx, fmaxf(fmaxf(v.x, v.y), fmaxf(v.z, v.w)));
            }
        }
    }
    for (int j = (n4 << 2) + blockIdx.x * NT + threadIdx.x; j < n; j += GRID * NT) {
        float v = xs[j];
        mn = fminf(mn, v); mx = fmaxf(mx, v);
    }
    #pragma unroll
    for (int o = 16; o > 0; o >>= 1) {
        mn = fminf(mn, __shfl_xor_sync(0xffffffffu, mn, o));
        mx = fmaxf(mx, __shfl_xor_sync(0xffffffffu, mx, o));
    }
    __shared__ float smn[NT / 32], smx[NT / 32];
    int w = threadIdx.x >> 5;
    if ((threadIdx.x & 31) == 0) { smn[w] = mn; smx[w] = mx; }
    __syncthreads();
    if (threadIdx.x == 0) {
        #pragma unroll
        for (int k = 1; k < NT / 32; k++) { mn = fminf(mn, smn[k]); mx = fmaxf(mx, smx[k]); }
        atomicMin(&g_min_u, fou(mn));
        atomicMax(&g_max_u, fou(mx));
    }
}

// ---------------- kernel 2: dmin/width + histogram affine coeffs ----------------
__global__ void k_prep1(const float* __restrict__ ct_p) {
    float mn = ouf(g_min_u), mx = ouf(g_max_u);
    float ct = ct_p[0];
    float a = ct * mn, b = ct * mx;                 // monotone map, handles ct<0
    float dmn = fminf(a, b) - 0.1f;
    float dmx = fmaxf(a, b) + 0.1f;
    float w = (dmx - dmn) / (float)NBINS;
    g_dmin  = dmn;
    g_width = w;
    float invw = 1.0f / w;
    g_histA = ct * invw;
    g_histB = -dmn * invw;
}

// ---------------- kernel 3: histogram via cumulative thresholds ----------------
__global__ void k_hist(const float4* __restrict__ x, int n4,
                       const float* __restrict__ xs, int n) {
    const float A = g_histA, B = g_histB;
    unsigned int s1 = 0, s2 = 0, s3 = 0, s4 = 0;
    int i = blockIdx.x * (NT * UN) + threadIdx.x;
    const int step = GRID * NT * UN;
    for (; i < n4; i += step) {
        #pragma unroll
        for (int k = 0; k < UN; k++) {
            int j = i + k * NT;
            if (j < n4) {
                float4 v = x[j];
                float q0 = fmaf(v.x, A, B);
                float q1 = fmaf(v.y, A, B);
                float q2 = fmaf(v.z, A, B);
                float q3 = fmaf(v.w, A, B);
                s1 += (q0 >= 1.0f) + (q1 >= 1.0f) + (q2 >= 1.0f) + (q3 >= 1.0f);
                s2 += (q0 >= 2.0f) + (q1 >= 2.0f) + (q2 >= 2.0f) + (q3 >= 2.0f);
                s3 += (q0 >= 3.0f) + (q1 >= 3.0f) + (q2 >= 3.0f) + (q3 >= 3.0f);
                s4 += (q0 >= 4.0f) + (q1 >= 4.0f) + (q2 >= 4.0f) + (q3 >= 4.0f);
            }
        }
    }
    for (int j = (n4 << 2) + blockIdx.x * NT + threadIdx.x; j < n; j += GRID * NT) {
        float q = fmaf(xs[j], A, B);
        s1 += (q >= 1.0f); s2 += (q >= 2.0f); s3 += (q >= 3.0f); s4 += (q >= 4.0f);
    }
    s1 = __reduce_add_sync(0xffffffffu, s1);
    s2 = __reduce_add_sync(0xffffffffu, s2);
    s3 = __reduce_add_sync(0xffffffffu, s3);
    s4 = __reduce_add_sync(0xffffffffu, s4);
    __shared__ unsigned int sc[4];
    if (threadIdx.x < 4) sc[threadIdx.x] = 0u;
    __syncthreads();
    if ((threadIdx.x & 31) == 0) {
        atomicAdd(&sc[0], s1); atomicAdd(&sc[1], s2);
        atomicAdd(&sc[2], s3); atomicAdd(&sc[3], s4);
    }
    __syncthreads();
    if (threadIdx.x < 4) atomicAdd(&g_s[threadIdx.x], sc[threadIdx.x]);
}

// ---------------- kernel 4: scalar table construction ----------------
__global__ void k_prep2(const float* __restrict__ params,
                        const float* __restrict__ ct_p,
                        const float* __restrict__ st_p, int n) {
    if (threadIdx.x != 0 || blockIdx.x != 0) return;
    const float dmin = g_dmin, wdt = g_width;
    const float ct = ct_p[0], st = st_p[0];

    // exact integer counts from cumulative thresholds
    unsigned int s1 = g_s[0], s2 = g_s[1], s3 = g_s[2], s4 = g_s[3];
    unsigned long long cnt[NBINS];
    cnt[0] = (unsigned long long)n - s1;
    cnt[1] = s1 - s2; cnt[2] = s2 - s3; cnt[3] = s3 - s4; cnt[4] = s4;

    // emulate fp32 +=1.0 accumulation: saturates exactly at 2^24
    float cf[NBINS];
    #pragma unroll
    for (int i = 0; i < NBINS; i++) {
        unsigned long long c = cnt[i];
        if (c > 16777216ull) c = 16777216ull;
        cf[i] = (float)c;
    }
    float s = cf[0] + cf[1] + cf[2] + cf[3] + cf[4];       // left-to-right fp32
    float accum[NBINS];
    float run = 0.0f;
    #pragma unroll
    for (int i = 0; i < NBINS; i++) {
        float prob = cf[i] / s;
        run += prob;
        accum[i] = run * (float)NBINS;
    }
    float edges[NBINS + 1], grid[NBINS];
    #pragma unroll
    for (int i = 0; i <= NBINS; i++) edges[i] = dmin + wdt * (float)i;
    #pragma unroll
    for (int i = 0; i < NBINS; i++) grid[i] = 0.5f * (edges[i + 1] + edges[i]);

    // per-segment (slope*ct, base) for index(x) = interp1d(grid, accum, x*ct)
    #pragma unroll
    for (int i = 0; i < NBINS - 1; i++) {
        float den = grid[i + 1] - grid[i];
        if (den == 0.0f) den = 1.0f;
        float slope = (accum[i + 1] - accum[i]) / den;
        g_tbl[2 * i]     = slope * ct;
        g_tbl[2 * i + 1] = accum[i] - slope * grid[i];
    }
    // frame = interp1d(accum, grid, arange(P))
    float frame[NBINS];
    #pragma unroll
    for (int q = 0; q < NBINS; q++) {
        float xq = (float)q;
        int ss = 0;
        #pragma unroll
        for (int j = 0; j < NBINS; j++) ss += (accum[j] < xq);
        int idx = min(max(ss - 1, 0), NBINS - 2);
        float den = accum[idx + 1] - accum[idx];
        if (den == 0.0f) den = 1.0f;
        frame[q] = grid[idx] + (grid[idx + 1] - grid[idx]) / den * (xq - accum[idx]);
    }
    float thp[NBINS], vep[NBINS];
    #pragma unroll
    for (int q = 0; q < NBINS; q++) {
        thp[q] = frame[q] + 0.001f * params[q];
        vep[q] = frame[q] + 0.001f * params[NBINS + q];
    }
    // 6 segments of (slope, intercept) in `index`, key = clamp(floor(index)+1, 0, 5)
    // k=0 : bi<=-1 -> constant p[0];  k=1..4 : bi=k-1 linear;  k=5 : bi>=4 -> constant p[4]
    #pragma unroll
    for (int k = 0; k < 6; k++) {
        float tS, tI, vS, vI;
        if (k == 0)      { tS = 0.0f; tI = thp[0]; vS = 0.0f; vI = vep[0]; }
        else if (k == 5) { tS = 0.0f; tI = thp[4]; vS = 0.0f; vI = vep[4]; }
        else {
            int bi = k - 1;
            tS = thp[bi + 1] - thp[bi]; tI = thp[bi] - tS * (float)bi;
            vS = vep[bi + 1] - vep[bi]; vI = vep[bi] - vS * (float)bi;
        }
        g_tbl[8 + 4 * k + 0] = tS;
        g_tbl[8 + 4 * k + 1] = tI;
        g_tbl[8 + 4 * k + 2] = vS;
        g_tbl[8 + 4 * k + 3] = vI;
    }
    float invw = 1.0f / wdt;
    g_tbl[32] = ct * invw;
    g_tbl[33] = -dmin * invw - 0.5f;
    g_tbl[34] = st * ct;
    g_tbl[35] = st;
}

// ---------------- kernel 5: elementwise apply ----------------
__device__ __forceinline__ float apply_one(float xv, const float2* sb, const float4* cf,
                                           float At, float c0, float stct, float st) {
    // stage 1: index(x) segment on uniform grid centers
    float t = fmaf(xv, At, c0);
    int idx = min(max(__float2int_rd(t), 0), NBINS - 2);
    float2 sp = sb[idx];
    float index = fmaf(xv, sp.x, sp.y);
    // stage 2: (theta, velo) linear-in-index segment
    int k = min(max(__float2int_rd(index) + 1, 0), 5);
    float4 c = cf[k];
    float th = fmaf(index, c.x, c.y);
    float ve = fmaf(index, c.z, c.w);
    float sn, cs;
    __sincosf(th, &sn, &cs);
    return fmaf(xv, stct * fmaf(ve, sn, 1.0f), st * (ve * cs));
}

__global__ void k_apply(const float4* __restrict__ x, float4* __restrict__ o, int n4,
                        const float* __restrict__ xs, float* __restrict__ os, int n) {
    __shared__ __align__(16) float tbl[36];
    if (threadIdx.x < 36) tbl[threadIdx.x] = g_tbl[threadIdx.x];
    __syncthreads();
    const float2* sb = (const float2*)tbl;          // 4 pairs
    const float4* cf = (const float4*)(tbl + 8);    // 6 quads
    const float At = tbl[32], c0 = tbl[33], stct = tbl[34], st = tbl[35];
    int i = blockIdx.x * (NT * UN) + threadIdx.x;
    const int step = GRID * NT * UN;
    for (; i < n4; i += step) {
        #pragma unroll
        for (int k = 0; k < UN; k++) {
            int j = i + k * NT;
            if (j < n4) {
                float4 v = __ldcs(&x[j]);
                float4 r;
                r.x = apply_one(v.x, sb, cf, At, c0, stct, st);
                r.y = apply_one(v.y, sb, cf, At, c0, stct, st);
                r.z = apply_one(v.z, sb, cf, At, c0, stct, st);
                r.w = apply_one(v.w, sb, cf, At, c0, stct, st);
                o[j] = r;
            }
        }
    }
    for (int j = (n4 << 2) + blockIdx.x * NT + threadIdx.x; j < n; j += GRID * NT)
        os[j] = apply_one(xs[j], sb, cf, At, c0, stct, st);
}

// ---------------- launch ----------------
extern "C" void kernel_launch(void* const* d_in, const int* in_sizes, int n_in,
                              void* d_out, int out_size) {
    const float* data   = (const float*)d_in[0];
    const float* params = (const float*)d_in[1];
    const float* ct     = (const float*)d_in[2];
    const float* st     = (const float*)d_in[3];
    float* out = (float*)d_out;
    int n  = in_sizes[0];
    int n4 = n >> 2;

    k_init<<<1, 32>>>();
    k_minmax<<<GRID, NT>>>((const float4*)data, n4, data, n);
    k_prep1<<<1, 1>>>(ct);
    k_hist<<<GRID, NT>>>((const float4*)data, n4, data, n);
    k_prep2<<<1, 1>>>(params, ct, st, n);
    k_apply<<<GRID, NT>>>((const float4*)data, (float4*)out, n4, data, out, n);
}

// round 8
// speedup vs baseline: 1.3277x; 1.0657x over previous
#include <cuda_runtime.h>

#define NBINS 5
#define NT    256
#define UN    4
#define GRID  2048
#define TILE  (NT * UN)   /* float4 units per tile = 1024 -> 16KB */

// ---------------- device scratch (no allocation allowed) ----------------
__device__ float g_pmin[GRID];
__device__ float g_pmax[GRID];
__device__ uint4 g_ps[GRID];          // per-block (s1,s2,s3,s4)
__device__ float g_dmin, g_width, g_histA, g_histB;
// table layout (36 floats):
//  [0..7]   (slopeA_i = slope_i*ct, base_i) for the 4 index(d) segments
//  [8..31]  6 x float4: (thSlope, thInt, veSlope, veInt) keyed by clamp(floor(index)+1,0,5)
//  [32] At = ct/width   [33] c0 = -dmin/width - 0.5   [34] stct = st*ct   [35] st
__device__ float g_tbl[36];

// ---------------- kernel 1: min/max of raw data (forward order) ----------------
__global__ void k_minmax(const float4* __restrict__ x, int n4,
                         const float* __restrict__ xs, int n, int ntiles) {
    float mn =  3.402823466e38f;
    float mx = -3.402823466e38f;
    for (int g = blockIdx.x; g < ntiles; g += GRID) {
        int base = g * TILE + threadIdx.x;
        float4 v0 = x[base];
        float4 v1 = x[base + NT];
        float4 v2 = x[base + 2 * NT];
        float4 v3 = x[base + 3 * NT];
        mn = fminf(mn, fminf(fminf(v0.x, v0.y), fminf(v0.z, v0.w)));
        mx = fmaxf(mx, fmaxf(fmaxf(v0.x, v0.y), fmaxf(v0.z, v0.w)));
        mn = fminf(mn, fminf(fminf(v1.x, v1.y), fminf(v1.z, v1.w)));
        mx = fmaxf(mx, fmaxf(fmaxf(v1.x, v1.y), fmaxf(v1.z, v1.w)));
        mn = fminf(mn, fminf(fminf(v2.x, v2.y), fminf(v2.z, v2.w)));
        mx = fmaxf(mx, fmaxf(fmaxf(v2.x, v2.y), fmaxf(v2.z, v2.w)));
        mn = fminf(mn, fminf(fminf(v3.x, v3.y), fminf(v3.z, v3.w)));
        mx = fmaxf(mx, fmaxf(fmaxf(v3.x, v3.y), fmaxf(v3.z, v3.w)));
    }
    int gtid = blockIdx.x * NT + threadIdx.x;
    for (int j = ntiles * TILE + gtid; j < n4; j += GRID * NT) {
        float4 v = x[j];
        mn = fminf(mn, fminf(fminf(v.x, v.y), fminf(v.z, v.w)));
        mx = fmaxf(mx, fmaxf(fmaxf(v.x, v.y), fmaxf(v.z, v.w)));
    }
    for (int j = (n4 << 2) + gtid; j < n; j += GRID * NT) {
        float v = xs[j];
        mn = fminf(mn, v); mx = fmaxf(mx, v);
    }
    #pragma unroll
    for (int o = 16; o > 0; o >>= 1) {
        mn = fminf(mn, __shfl_xor_sync(0xffffffffu, mn, o));
        mx = fmaxf(mx, __shfl_xor_sync(0xffffffffu, mx, o));
    }
    __shared__ float smn[NT / 32], smx[NT / 32];
    int w = threadIdx.x >> 5;
    if ((threadIdx.x & 31) == 0) { smn[w] = mn; smx[w] = mx; }
    __syncthreads();
    if (threadIdx.x == 0) {
        #pragma unroll
        for (int k = 1; k < NT / 32; k++) { mn = fminf(mn, smn[k]); mx = fmaxf(mx, smx[k]); }
        g_pmin[blockIdx.x] = mn;
        g_pmax[blockIdx.x] = mx;
    }
}

// ---------------- kernel 2: reduce partials -> dmin/width + hist affine ----------------
__global__ void k_prep1(const float* __restrict__ ct_p) {
    float mn =  3.402823466e38f;
    float mx = -3.402823466e38f;
    for (int i = threadIdx.x; i < GRID; i += NT) {
        mn = fminf(mn, g_pmin[i]);
        mx = fmaxf(mx, g_pmax[i]);
    }
    #pragma unroll
    for (int o = 16; o > 0; o >>= 1) {
        mn = fminf(mn, __shfl_xor_sync(0xffffffffu, mn, o));
        mx = fmaxf(mx, __shfl_xor_sync(0xffffffffu, mx, o));
    }
    __shared__ float smn[NT / 32], smx[NT / 32];
    int w = threadIdx.x >> 5;
    if ((threadIdx.x & 31) == 0) { smn[w] = mn; smx[w] = mx; }
    __syncthreads();
    if (threadIdx.x == 0) {
        #pragma unroll
        for (int k = 1; k < NT / 32; k++) { mn = fminf(mn, smn[k]); mx = fmaxf(mx, smx[k]); }
        float ct = ct_p[0];
        float a = ct * mn, b = ct * mx;             // monotone map, handles ct<0
        float dmn = fminf(a, b) - 0.1f;
        float dmx = fmaxf(a, b) + 0.1f;
        float wd = (dmx - dmn) / (float)NBINS;
        g_dmin  = dmn;
        g_width = wd;
        float invw = 1.0f / wd;
        g_histA = ct * invw;
        g_histB = -dmn * invw;
    }
}

// ---------------- kernel 3: histogram via cumulative thresholds (REVERSE order) ----------------
__device__ __forceinline__ void hist4(float4 v, float A, float B,
                                      unsigned int& s1, unsigned int& s2,
                                      unsigned int& s3, unsigned int& s4) {
    float q0 = fmaf(v.x, A, B);
    float q1 = fmaf(v.y, A, B);
    float q2 = fmaf(v.z, A, B);
    float q3 = fmaf(v.w, A, B);
    s1 += (q0 >= 1.0f) + (q1 >= 1.0f) + (q2 >= 1.0f) + (q3 >= 1.0f);
    s2 += (q0 >= 2.0f) + (q1 >= 2.0f) + (q2 >= 2.0f) + (q3 >= 2.0f);
    s3 += (q0 >= 3.0f) + (q1 >= 3.0f) + (q2 >= 3.0f) + (q3 >= 3.0f);
    s4 += (q0 >= 4.0f) + (q1 >= 4.0f) + (q2 >= 4.0f) + (q3 >= 4.0f);
}

__global__ void k_hist(const float4* __restrict__ x, int n4,
                       const float* __restrict__ xs, int n, int ntiles) {
    const float A = g_histA, B = g_histB;
    unsigned int s1 = 0, s2 = 0, s3 = 0, s4 = 0;
    for (int g = blockIdx.x; g < ntiles; g += GRID) {
        int base = (ntiles - 1 - g) * TILE + threadIdx.x;   // reverse traversal -> L2 hits
        float4 v0 = x[base];
        float4 v1 = x[base + NT];
        float4 v2 = x[base + 2 * NT];
        float4 v3 = x[base + 3 * NT];
        hist4(v0, A, B, s1, s2, s3, s4);
        hist4(v1, A, B, s1, s2, s3, s4);
        hist4(v2, A, B, s1, s2, s3, s4);
        hist4(v3, A, B, s1, s2, s3, s4);
    }
    int gtid = blockIdx.x * NT + threadIdx.x;
    for (int j = ntiles * TILE + gtid; j < n4; j += GRID * NT)
        hist4(x[j], A, B, s1, s2, s3, s4);
    for (int j = (n4 << 2) + gtid; j < n; j += GRID * NT) {
        float q = fmaf(xs[j], A, B);
        s1 += (q >= 1.0f); s2 += (q >= 2.0f); s3 += (q >= 3.0f); s4 += (q >= 4.0f);
    }
    s1 = __reduce_add_sync(0xffffffffu, s1);
    s2 = __reduce_add_sync(0xffffffffu, s2);
    s3 = __reduce_add_sync(0xffffffffu, s3);
    s4 = __reduce_add_sync(0xffffffffu, s4);
    __shared__ unsigned int sc[4];
    if (threadIdx.x < 4) sc[threadIdx.x] = 0u;
    __syncthreads();
    if ((threadIdx.x & 31) == 0) {
        atomicAdd(&sc[0], s1); atomicAdd(&sc[1], s2);
        atomicAdd(&sc[2], s3); atomicAdd(&sc[3], s4);
    }
    __syncthreads();
    if (threadIdx.x == 0) g_ps[blockIdx.x] = make_uint4(sc[0], sc[1], sc[2], sc[3]);
}

// ---------------- kernel 4: reduce hist partials + build tables ----------------
__global__ void k_prep2(const float* __restrict__ params,
                        const float* __restrict__ ct_p,
                        const float* __restrict__ st_p, int n) {
    unsigned int a1 = 0, a2 = 0, a3 = 0, a4 = 0;
    for (int i = threadIdx.x; i < GRID; i += NT) {
        uint4 p = g_ps[i];
        a1 += p.x; a2 += p.y; a3 += p.z; a4 += p.w;
    }
    a1 = __reduce_add_sync(0xffffffffu, a1);
    a2 = __reduce_add_sync(0xffffffffu, a2);
    a3 = __reduce_add_sync(0xffffffffu, a3);
    a4 = __reduce_add_sync(0xffffffffu, a4);
    __shared__ unsigned int sc[4][NT / 32];
    int w = threadIdx.x >> 5;
    if ((threadIdx.x & 31) == 0) { sc[0][w] = a1; sc[1][w] = a2; sc[2][w] = a3; sc[3][w] = a4; }
    __syncthreads();
    if (threadIdx.x != 0) return;
    #pragma unroll
    for (int k = 1; k < NT / 32; k++) { a1 += sc[0][k]; a2 += sc[1][k]; a3 += sc[2][k]; a4 += sc[3][k]; }

    const float dmin = g_dmin, wdt = g_width;
    const float ct = ct_p[0], st = st_p[0];

    unsigned long long cnt[NBINS];
    cnt[0] = (unsigned long long)n - a1;
    cnt[1] = a1 - a2; cnt[2] = a2 - a3; cnt[3] = a3 - a4; cnt[4] = a4;

    // emulate fp32 +=1.0 accumulation: saturates exactly at 2^24
    float cf[NBINS];
    #pragma unroll
    for (int i = 0; i < NBINS; i++) {
        unsigned long long c = cnt[i];
        if (c > 16777216ull) c = 16777216ull;
        cf[i] = (float)c;
    }
    float s = cf[0] + cf[1] + cf[2] + cf[3] + cf[4];       // left-to-right fp32
    float accum[NBINS];
    float run = 0.0f;
    #pragma unroll
    for (int i = 0; i < NBINS; i++) {
        float prob = cf[i] / s;
        run += prob;
        accum[i] = run * (float)NBINS;
    }
    float edges[NBINS + 1], grid[NBINS];
    #pragma unroll
    for (int i = 0; i <= NBINS; i++) edges[i] = dmin + wdt * (float)i;
    #pragma unroll
    for (int i = 0; i < NBINS; i++) grid[i] = 0.5f * (edges[i + 1] + edges[i]);

    // per-segment (slope*ct, base) for index(x) = interp1d(grid, accum, x*ct)
    #pragma unroll
    for (int i = 0; i < NBINS - 1; i++) {
        float den = grid[i + 1] - grid[i];
        if (den == 0.0f) den = 1.0f;
        float slope = (accum[i + 1] - accum[i]) / den;
        g_tbl[2 * i]     = slope * ct;
        g_tbl[2 * i + 1] = accum[i] - slope * grid[i];
    }
    // frame = interp1d(accum, grid, arange(P))
    float frame[NBINS];
    #pragma unroll
    for (int q = 0; q < NBINS; q++) {
        float xq = (float)q;
        int ss = 0;
        #pragma unroll
        for (int j = 0; j < NBINS; j++) ss += (accum[j] < xq);
        int idx = min(max(ss - 1, 0), NBINS - 2);
        float den = accum[idx + 1] - accum[idx];
        if (den == 0.0f) den = 1.0f;
        frame[q] = grid[idx] + (grid[idx + 1] - grid[idx]) / den * (xq - accum[idx]);
    }
    float thp[NBINS], vep[NBINS];
    #pragma unroll
    for (int q = 0; q < NBINS; q++) {
        thp[q] = frame[q] + 0.001f * params[q];
        vep[q] = frame[q] + 0.001f * params[NBINS + q];
    }
    // 6 segments of (slope, intercept) in `index`, key = clamp(floor(index)+1, 0, 5)
    #pragma unroll
    for (int k = 0; k < 6; k++) {
        float tS, tI, vS, vI;
        if (k == 0)      { tS = 0.0f; tI = thp[0]; vS = 0.0f; vI = vep[0]; }
        else if (k == 5) { tS = 0.0f; tI = thp[4]; vS = 0.0f; vI = vep[4]; }
        else {
            int bi = k - 1;
            tS = thp[bi + 1] - thp[bi]; tI = thp[bi] - tS * (float)bi;
            vS = vep[bi + 1] - vep[bi]; vI = vep[bi] - vS * (float)bi;
        }
        g_tbl[8 + 4 * k + 0] = tS;
        g_tbl[8 + 4 * k + 1] = tI;
        g_tbl[8 + 4 * k + 2] = vS;
        g_tbl[8 + 4 * k + 3] = vI;
    }
    float invw = 1.0f / wdt;
    g_tbl[32] = ct * invw;
    g_tbl[33] = -dmin * invw - 0.5f;
    g_tbl[34] = st * ct;
    g_tbl[35] = st;
}

// ---------------- kernel 5: elementwise apply (forward order, streaming stores) ----------------
__device__ __forceinline__ float apply_one(float xv, const float2* sb, const float4* cf,
                                           float At, float c0, float stct, float st) {
    float t = fmaf(xv, At, c0);
    int idx = min(max(__float2int_rd(t), 0), NBINS - 2);
    float2 sp = sb[idx];
    float index = fmaf(xv, sp.x, sp.y);
    int k = min(max(__float2int_rd(index) + 1, 0), 5);
    float4 c = cf[k];
    float th = fmaf(index, c.x, c.y);
    float ve = fmaf(index, c.z, c.w);
    float sn, cs;
    __sincosf(th, &sn, &cs);
    return fmaf(xv, stct * fmaf(ve, sn, 1.0f), st * (ve * cs));
}

__global__ void k_apply(const float4* __restrict__ x, float4* __restrict__ o, int n4,
                        const float* __restrict__ xs, float* __restrict__ os, int n, int ntiles) {
    __shared__ __align__(16) float tbl[36];
    if (threadIdx.x < 36) tbl[threadIdx.x] = g_tbl[threadIdx.x];
    __syncthreads();
    const float2* sb = (const float2*)tbl;          // 4 pairs
    const float4* cf = (const float4*)(tbl + 8);    // 6 quads
    const float At = tbl[32], c0 = tbl[33], stct = tbl[34], st = tbl[35];
    for (int g = blockIdx.x; g < ntiles; g += GRID) {
        int base = g * TILE + threadIdx.x;           // forward = reverse of hist -> L2 hits
        float4 v0 = __ldcs(&x[base]);
        float4 v1 = __ldcs(&x[base + NT]);
        float4 v2 = __ldcs(&x[base + 2 * NT]);
        float4 v3 = __ldcs(&x[base + 3 * NT]);
        float4 r0, r1, r2, r3;
        r0.x = apply_one(v0.x, sb, cf, At, c0, stct, st);
        r0.y = apply_one(v0.y, sb, cf, At, c0, stct, st);
        r0.z = apply_one(v0.z, sb, cf, At, c0, stct, st);
        r0.w = apply_one(v0.w, sb, cf, At, c0, stct, st);
        r1.x = apply_one(v1.x, sb, cf, At, c0, stct, st);
        r1.y = apply_one(v1.y, sb, cf, At, c0, stct, st);
        r1.z = apply_one(v1.z, sb, cf, At, c0, stct, st);
        r1.w = apply_one(v1.w, sb, cf, At, c0, stct, st);
        r2.x = apply_one(v2.x, sb, cf, At, c0, stct, st);
        r2.y = apply_one(v2.y, sb, cf, At, c0, stct, st);
        r2.z = apply_one(v2.z, sb, cf, At, c0, stct, st);
        r2.w = apply_one(v2.w, sb, cf, At, c0, stct, st);
        r3.x = apply_one(v3.x, sb, cf, At, c0, stct, st);
        r3.y = apply_one(v3.y, sb, cf, At, c0, stct, st);
        r3.z = apply_one(v3.z, sb, cf, At, c0, stct, st);
        r3.w = apply_one(v3.w, sb, cf, At, c0, stct, st);
        __stcs(&o[base], r0);
        __stcs(&o[base + NT], r1);
        __stcs(&o[base + 2 * NT], r2);
        __stcs(&o[base + 3 * NT], r3);
    }
    int gtid = blockIdx.x * NT + threadIdx.x;
    for (int j = ntiles * TILE + gtid; j < n4; j += GRID * NT) {
        float4 v = __ldcs(&x[j]);
        float4 r;
        r.x = apply_one(v.x, sb, cf, At, c0, stct, st);
        r.y = apply_one(v.y, sb, cf, At, c0, stct, st);
        r.z = apply_one(v.z, sb, cf, At, c0, stct, st);
        r.w = apply_one(v.w, sb, cf, At, c0, stct, st);
        __stcs(&o[j], r);
    }
    for (int j = (n4 << 2) + gtid; j < n; j += GRID * NT)
        os[j] = apply_one(xs[j], sb, cf, At, c0, stct, st);
}

// ---------------- launch ----------------
extern "C" void kernel_launch(void* const* d_in, const int* in_sizes, int n_in,
                              void* d_out, int out_size) {
    const float* data   = (const float*)d_in[0];
    const float* params = (const float*)d_in[1];
    const float* ct     = (const float*)d_in[2];
    const float* st     = (const float*)d_in[3];
    float* out = (float*)d_out;
    int n      = in_sizes[0];
    int n4     = n >> 2;
    int ntiles = n4 / TILE;

    k_minmax<<<GRID, NT>>>((const float4*)data, n4, data, n, ntiles);
    k_prep1<<<1, NT>>>(ct);
    k_hist<<<GRID, NT>>>((const float4*)data, n4, data, n, ntiles);
    k_prep2<<<1, NT>>>(params, ct, st, n);
    k_apply<<<GRID, NT>>>((const float4*)data, (float4*)out, n4, data, out, n, ntiles);
}

// round 10
// speedup vs baseline: 1.3453x; 1.0132x over previous
#include <cuda_runtime.h>

#define NBINS 5
#define NT    256
#define UN2   8                 /* minmax/hist unroll: 8 x float4 per thread */
#define UN    4                 /* apply unroll */
#define GRID  2048
#define TILE2 (NT * UN2)        /* 2048 float4 = 32KB */
#define TILE  (NT * UN)         /* 1024 float4 = 16KB */

// ---------------- device scratch (no allocation allowed) ----------------
__device__ float g_pmin[GRID];
__device__ float g_pmax[GRID];
__device__ uint4 g_ps[GRID];            // per-block (s1,s2,s3,s4)
__device__ unsigned int g_c1, g_c2;     // last-block tickets (self-resetting)
__device__ float g_dmin, g_width, g_histA, g_histB;
// table layout (36 floats):
//  [0..7]   (slopeA_i = slope_i*ct, base_i) for the 4 index(d) segments
//  [8..31]  6 x float4: (thSlope, thInt, veSlope, veInt) keyed by clamp(floor(index)+1,0,5)
//  [32] At = ct/width   [33] c0 = -dmin/width - 0.5   [34] stct = st*ct   [35] st
__device__ float g_tbl[36];

// ---------------- kernel 1: min/max (forward) + fused prep1 in last block ----------------
__global__ void k_minmax(const float4* __restrict__ x, int n4,
                         const float* __restrict__ xs, int n, int ntiles,
                         const float* __restrict__ ct_p) {
    float mn =  3.402823466e38f;
    float mx = -3.402823466e38f;
    for (int g = blockIdx.x; g < ntiles; g += GRID) {
        int base = g * TILE2 + threadIdx.x;
        #pragma unroll
        for (int k = 0; k < UN2; k++) {
            float4 v = x[base + k * NT];
            mn = fminf(mn, fminf(fminf(v.x, v.y), fminf(v.z, v.w)));
            mx = fmaxf(mx, fmaxf(fmaxf(v.x, v.y), fmaxf(v.z, v.w)));
        }
    }
    int gtid = blockIdx.x * NT + threadIdx.x;
    for (int j = ntiles * TILE2 + gtid; j < n4; j += GRID * NT) {
        float4 v = x[j];
        mn = fminf(mn, fminf(fminf(v.x, v.y), fminf(v.z, v.w)));
        mx = fmaxf(mx, fmaxf(fmaxf(v.x, v.y), fmaxf(v.z, v.w)));
    }
    for (int j = (n4 << 2) + gtid; j < n; j += GRID * NT) {
        float v = xs[j];
        mn = fminf(mn, v); mx = fmaxf(mx, v);
    }
    #pragma unroll
    for (int o = 16; o > 0; o >>= 1) {
        mn = fminf(mn, __shfl_xor_sync(0xffffffffu, mn, o));
        mx = fmaxf(mx, __shfl_xor_sync(0xffffffffu, mx, o));
    }
    __shared__ float smn[NT / 32], smx[NT / 32];
    __shared__ unsigned int s_last;
    int w = threadIdx.x >> 5;
    if ((threadIdx.x & 31) == 0) { smn[w] = mn; smx[w] = mx; }
    __syncthreads();
    if (threadIdx.x == 0) {
        #pragma unroll
        for (int k = 1; k < NT / 32; k++) { mn = fminf(mn, smn[k]); mx = fmaxf(mx, smx[k]); }
        g_pmin[blockIdx.x] = mn;
        g_pmax[blockIdx.x] = mx;
        __threadfence();
        unsigned int o = atomicAdd(&g_c1, 1u);
        s_last = (o == gridDim.x - 1) ? 1u : 0u;
    }
    __syncthreads();
    if (!s_last) return;

    // ---- fused prep1: reduce partials -> dmin/width + hist affine ----
    __threadfence();
    mn =  3.402823466e38f;
    mx = -3.402823466e38f;
    for (int i = threadIdx.x; i < GRID; i += NT) {
        mn = fminf(mn, g_pmin[i]);
        mx = fmaxf(mx, g_pmax[i]);
    }
    #pragma unroll
    for (int o = 16; o > 0; o >>= 1) {
        mn = fminf(mn, __shfl_xor_sync(0xffffffffu, mn, o));
        mx = fmaxf(mx, __shfl_xor_sync(0xffffffffu, mx, o));
    }
    if ((threadIdx.x & 31) == 0) { smn[w] = mn; smx[w] = mx; }
    __syncthreads();
    if (threadIdx.x == 0) {
        #pragma unroll
        for (int k = 1; k < NT / 32; k++) { mn = fminf(mn, smn[k]); mx = fmaxf(mx, smx[k]); }
        float ct = ct_p[0];
        float a = ct * mn, b = ct * mx;             // monotone map, handles ct<0
        float dmn = fminf(a, b) - 0.1f;
        float dmx = fmaxf(a, b) + 0.1f;
        float wd = (dmx - dmn) / (float)NBINS;
        g_dmin  = dmn;
        g_width = wd;
        float invw = 1.0f / wd;
        g_histA = ct * invw;
        g_histB = -dmn * invw;
        atomicExch(&g_c1, 0u);                       // reset for next replay
    }
}

// ---------------- kernel 2: histogram (REVERSE) + fused prep2 in last block ----------------
__device__ __forceinline__ void hist4(float4 v, float A, float B,
                                      unsigned int& s1, unsigned int& s2,
                                      unsigned int& s3, unsigned int& s4) {
    float q0 = fmaf(v.x, A, B);
    float q1 = fmaf(v.y, A, B);
    float q2 = fmaf(v.z, A, B);
    float q3 = fmaf(v.w, A, B);
    s1 += (q0 >= 1.0f) + (q1 >= 1.0f) + (q2 >= 1.0f) + (q3 >= 1.0f);
    s2 += (q0 >= 2.0f) + (q1 >= 2.0f) + (q2 >= 2.0f) + (q3 >= 2.0f);
    s3 += (q0 >= 3.0f) + (q1 >= 3.0f) + (q2 >= 3.0f) + (q3 >= 3.0f);
    s4 += (q0 >= 4.0f) + (q1 >= 4.0f) + (q2 >= 4.0f) + (q3 >= 4.0f);
}

__global__ void k_hist(const float4* __restrict__ x, int n4,
                       const float* __restrict__ xs, int n, int ntiles,
                       const float* __restrict__ params,
                       const float* __restrict__ ct_p,
                       const float* __restrict__ st_p) {
    const float A = g_histA, B = g_histB;
    unsigned int s1 = 0, s2 = 0, s3 = 0, s4 = 0;
    for (int g = blockIdx.x; g < ntiles; g += GRID) {
        int base = (ntiles - 1 - g) * TILE2 + threadIdx.x;  // reverse traversal -> L2 hits
        #pragma unroll
        for (int k = 0; k < UN2; k++)
            hist4(x[base + k * NT], A, B, s1, s2, s3, s4);
    }
    int gtid = blockIdx.x * NT + threadIdx.x;
    for (int j = ntiles * TILE2 + gtid; j < n4; j += GRID * NT)
        hist4(x[j], A, B, s1, s2, s3, s4);
    for (int j = (n4 << 2) + gtid; j < n; j += GRID * NT) {
        float q = fmaf(xs[j], A, B);
        s1 += (q >= 1.0f); s2 += (q >= 2.0f); s3 += (q >= 3.0f); s4 += (q >= 4.0f);
    }
    s1 = __reduce_add_sync(0xffffffffu, s1);
    s2 = __reduce_add_sync(0xffffffffu, s2);
    s3 = __reduce_add_sync(0xffffffffu, s3);
    s4 = __reduce_add_sync(0xffffffffu, s4);
    __shared__ unsigned int sc[4];
    __shared__ unsigned int s_last;
    if (threadIdx.x < 4) sc[threadIdx.x] = 0u;
    __syncthreads();
    if ((threadIdx.x & 31) == 0) {
        atomicAdd(&sc[0], s1); atomicAdd(&sc[1], s2);
        atomicAdd(&sc[2], s3); atomicAdd(&sc[3], s4);
    }
    __syncthreads();
    if (threadIdx.x == 0) {
        g_ps[blockIdx.x] = make_uint4(sc[0], sc[1], sc[2], sc[3]);
        __threadfence();
        unsigned int o = atomicAdd(&g_c2, 1u);
        s_last = (o == gridDim.x - 1) ? 1u : 0u;
    }
    __syncthreads();
    if (!s_last) return;

    // ---- fused prep2: reduce hist partials + build tables ----
    __threadfence();
    __shared__ float s_in[12];   // [0..9]=params, [10]=ct, [11]=st  (prefetch, overlap)
    if (threadIdx.x < 10) s_in[threadIdx.x] = params[threadIdx.x];
    else if (threadIdx.x == 10) s_in[10] = ct_p[0];
    else if (threadIdx.x == 11) s_in[11] = st_p[0];

    unsigned int a1 = 0, a2 = 0, a3 = 0, a4 = 0;
    for (int i = threadIdx.x; i < GRID; i += NT) {
        uint4 p = g_ps[i];
        a1 += p.x; a2 += p.y; a3 += p.z; a4 += p.w;
    }
    a1 = __reduce_add_sync(0xffffffffu, a1);
    a2 = __reduce_add_sync(0xffffffffu, a2);
    a3 = __reduce_add_sync(0xffffffffu, a3);
    a4 = __reduce_add_sync(0xffffffffu, a4);
    __shared__ unsigned int sr[4][NT / 32];
    int w = threadIdx.x >> 5;
    if ((threadIdx.x & 31) == 0) { sr[0][w] = a1; sr[1][w] = a2; sr[2][w] = a3; sr[3][w] = a4; }
    __syncthreads();
    if (threadIdx.x != 0) return;
    #pragma unroll
    for (int k = 1; k < NT / 32; k++) { a1 += sr[0][k]; a2 += sr[1][k]; a3 += sr[2][k]; a4 += sr[3][k]; }

    const float dmin = g_dmin, wdt = g_width;
    const float ct = s_in[10], st = s_in[11];

    unsigned long long cnt[NBINS];
    cnt[0] = (unsigned long long)n - a1;
    cnt[1] = a1 - a2; cnt[2] = a2 - a3; cnt[3] = a3 - a4; cnt[4] = a4;

    // emulate fp32 +=1.0 accumulation: saturates exactly at 2^24
    float cf[NBINS];
    #pragma unroll
    for (int i = 0; i < NBINS; i++) {
        unsigned long long c = cnt[i];
        if (c > 16777216ull) c = 16777216ull;
        cf[i] = (float)c;
    }
    float s = cf[0] + cf[1] + cf[2] + cf[3] + cf[4];       // left-to-right fp32
    float accum[NBINS];
    float run = 0.0f;
    #pragma unroll
    for (int i = 0; i < NBINS; i++) {
        float prob = cf[i] / s;
        run += prob;
        accum[i] = run * (float)NBINS;
    }
    float edges[NBINS + 1], grid[NBINS];
    #pragma unroll
    for (int i = 0; i <= NBINS; i++) edges[i] = dmin + wdt * (float)i;
    #pragma unroll
    for (int i = 0; i < NBINS; i++) grid[i] = 0.5f * (edges[i + 1] + edges[i]);

    // per-segment (slope*ct, base) for index(x) = interp1d(grid, accum, x*ct)
    #pragma unroll
    for (int i = 0; i < NBINS - 1; i++) {
        float den = grid[i + 1] - grid[i];
        if (den == 0.0f) den = 1.0f;
        float slope = (accum[i + 1] - accum[i]) / den;
        g_tbl[2 * i]     = slope * ct;
        g_tbl[2 * i + 1] = accum[i] - slope * grid[i];
    }
    // frame = interp1d(accum, grid, arange(P))
    float frame[NBINS];
    #pragma unroll
    for (int q = 0; q < NBINS; q++) {
        float xq = (float)q;
        int ss = 0;
        #pragma unroll
        for (int j = 0; j < NBINS; j++) ss += (accum[j] < xq);
        int idx = min(max(ss - 1, 0), NBINS - 2);
        float den = accum[idx + 1] - accum[idx];
        if (den == 0.0f) den = 1.0f;
        frame[q] = grid[idx] + (grid[idx + 1] - grid[idx]) / den * (xq - accum[idx]);
    }
    float thp[NBINS], vep[NBINS];
    #pragma unroll
    for (int q = 0; q < NBINS; q++) {
        thp[q] = frame[q] + 0.001f * s_in[q];
        vep[q] = frame[q] + 0.001f * s_in[NBINS + q];
    }
    // 6 segments of (slope, intercept) in `index`, key = clamp(floor(index)+1, 0, 5)
    #pragma unroll
    for (int k = 0; k < 6; k++) {
        float tS, tI, vS, vI;
        if (k == 0)      { tS = 0.0f; tI = thp[0]; vS = 0.0f; vI = vep[0]; }
        else if (k == 5) { tS = 0.0f; tI = thp[4]; vS = 0.0f; vI = vep[4]; }
        else {
            int bi = k - 1;
            tS = thp[bi + 1] - thp[bi]; tI = thp[bi] - tS * (float)bi;
            vS = vep[bi + 1] - vep[bi]; vI = vep[bi] - vS * (float)bi;
        }
        g_tbl[8 + 4 * k + 0] = tS;
        g_tbl[8 + 4 * k + 1] = tI;
        g_tbl[8 + 4 * k + 2] = vS;
        g_tbl[8 + 4 * k + 3] = vI;
    }
    float invw = 1.0f / wdt;
    g_tbl[32] = ct * invw;
    g_tbl[33] = -dmin * invw - 0.5f;
    g_tbl[34] = st * ct;
    g_tbl[35] = st;
    atomicExch(&g_c2, 0u);                           // reset for next replay
}

// ---------------- kernel 3: elementwise apply (forward, streaming) ----------------
__device__ __forceinline__ float apply_one(float xv, const float2* sb, const float4* cf,
                                           float At, float c0, float stct, float st) {
    float t = fmaf(xv, At, c0);
    int idx = min(max(__float2int_rd(t), 0), NBINS - 2);
    float2 sp = sb[idx];
    float index = fmaf(xv, sp.x, sp.y);
    int k = min(max(__float2int_rd(index) + 1, 0), 5);
    float4 c = cf[k];
    float th = fmaf(index, c.x, c.y);
    float ve = fmaf(index, c.z, c.w);
    float sn, cs;
    __sincosf(th, &sn, &cs);
    return fmaf(xv, stct * fmaf(ve, sn, 1.0f), st * (ve * cs));
}

__global__ void k_apply(const float4* __restrict__ x, float4* __restrict__ o, int n4,
                        const float* __restrict__ xs, float* __restrict__ os, int n, int ntiles) {
    __shared__ __align__(16) float tbl[36];
    if (threadIdx.x < 36) tbl[threadIdx.x] = g_tbl[threadIdx.x];
    __syncthreads();
    const float2* sb = (const float2*)tbl;          // 4 pairs
    const float4* cf = (const float4*)(tbl + 8);    // 6 quads
    const float At = tbl[32], c0 = tbl[33], stct = tbl[34], st = tbl[35];
    for (int g = blockIdx.x; g < ntiles; g += GRID) {
        int base = g * TILE + threadIdx.x;           // forward = reverse of hist -> L2 hits
        float4 v0 = __ldcs(&x[base]);
        float4 v1 = __ldcs(&x[base + NT]);
        float4 v2 = __ldcs(&x[base + 2 * NT]);
        float4 v3 = __ldcs(&x[base + 3 * NT]);
        float4 r0, r1, r2, r3;
        r0.x = apply_one(v0.x, sb, cf, At, c0, stct, st);
        r0.y = apply_one(v0.y, sb, cf, At, c0, stct, st);
        r0.z = apply_one(v0.z, sb, cf, At, c0, stct, st);
        r0.w = apply_one(v0.w, sb, cf, At, c0, stct, st);
        r1.x = apply_one(v1.x, sb, cf, At, c0, stct, st);
        r1.y = apply_one(v1.y, sb, cf, At, c0, stct, st);
        r1.z = apply_one(v1.z, sb, cf, At, c0, stct, st);
        r1.w = apply_one(v1.w, sb, cf, At, c0, stct, st);
        r2.x = apply_one(v2.x, sb, cf, At, c0, stct, st);
        r2.y = apply_one(v2.y, sb, cf, At, c0, stct, st);
        r2.z = apply_one(v2.z, sb, cf, At, c0, stct, st);
        r2.w = apply_one(v2.w, sb, cf, At, c0, stct, st);
        r3.x = apply_one(v3.x, sb, cf, At, c0, stct, st);
        r3.y = apply_one(v3.y, sb, cf, At, c0, stct, st);
        r3.z = apply_one(v3.z, sb, cf, At, c0, stct, st);
        r3.w = apply_one(v3.w, sb, cf, At, c0, stct, st);
        __stcs(&o[base], r0);
        __stcs(&o[base + NT], r1);
        __stcs(&o[base + 2 * NT], r2);
        __stcs(&o[base + 3 * NT], r3);
    }
    int gtid = blockIdx.x * NT + threadIdx.x;
    for (int j = ntiles * TILE + gtid; j < n4; j += GRID * NT) {
        float4 v = __ldcs(&x[j]);
        float4 r;
        r.x = apply_one(v.x, sb, cf, At, c0, stct, st);
        r.y = apply_one(v.y, sb, cf, At, c0, stct, st);
        r.z = apply_one(v.z, sb, cf, At, c0, stct, st);
        r.w = apply_one(v.w, sb, cf, At, c0, stct, st);
        __stcs(&o[j], r);
    }
    for (int j = (n4 << 2) + gtid; j < n; j += GRID * NT)
        os[j] = apply_one(xs[j], sb, cf, At, c0, stct, st);
}

// ---------------- launch ----------------
extern "C" void kernel_launch(void* const* d_in, const int* in_sizes, int n_in,
                              void* d_out, int out_size) {
    const float* data   = (const float*)d_in[0];
    const float* params = (const float*)d_in[1];
    const float* ct     = (const float*)d_in[2];
    const float* st     = (const float*)d_in[3];
    float* out = (float*)d_out;
    int n       = in_sizes[0];
    int n4      = n >> 2;
    int ntiles2 = n4 / TILE2;
    int ntiles  = n4 / TILE;

    k_minmax<<<GRID, NT>>>((const float4*)data, n4, data, n, ntiles2, ct);
    k_hist<<<GRID, NT>>>((const float4*)data, n4, data, n, ntiles2, params, ct, st);
    k_apply<<<GRID, NT>>>((const float4*)data, (float4*)out, n4, data, out, n, ntiles);
}

// round 12
// speedup vs baseline: 1.4332x; 1.0654x over previous
#include <cuda_runtime.h>

#define NBINS 5
#define NT    256
#define UN2   8                 /* fused pass unroll: 8 x float4 per thread */
#define UN    4                 /* apply unroll */
#define GRID2 592               /* 148 SMs x 4 blocks -- all resident (launch_bounds) */
#define GRIDA 2048              /* apply grid */
#define TILE2 (NT * UN2)        /* 2048 float4 = 32KB */
#define TILE  (NT * UN)         /* 1024 float4 = 16KB */

// ---------------- device scratch (no allocation allowed) ----------------
__device__ float g_pmin[GRID2];
__device__ float g_pmax[GRID2];
__device__ uint4 g_ps[GRID2];               // per-block (s1,s2,s3,s4)
__device__ volatile unsigned int g_bar;     // grid barrier (self-resetting)
__device__ unsigned int g_tk;               // last-block ticket (self-resetting)
// table layout (36 floats):
//  [0..7]   (slopeA_i = slope_i*ct, base_i) for the 4 index(d) segments
//  [8..31]  6 x float4: (thSlope, thInt, veSlope, veInt) keyed by clamp(floor(index)+1,0,5)
//  [32] At = ct/width   [33] c0 = -dmin/width - 0.5   [34] stct = st*ct   [35] st
__device__ float g_tbl[36];

// ---------------- fused kernel: minmax (fwd) -> grid barrier -> hist (own-chunk reverse) ----
__device__ __forceinline__ void hist4(float4 v, float A, float B,
                                      unsigned int& s1, unsigned int& s2,
                                      unsigned int& s3, unsigned int& s4) {
    float q0 = fmaf(v.x, A, B);
    float q1 = fmaf(v.y, A, B);
    float q2 = fmaf(v.z, A, B);
    float q3 = fmaf(v.w, A, B);
    s1 += (q0 >= 1.0f) + (q1 >= 1.0f) + (q2 >= 1.0f) + (q3 >= 1.0f);
    s2 += (q0 >= 2.0f) + (q1 >= 2.0f) + (q2 >= 2.0f) + (q3 >= 2.0f);
    s3 += (q0 >= 3.0f) + (q1 >= 3.0f) + (q2 >= 3.0f) + (q3 >= 3.0f);
    s4 += (q0 >= 4.0f) + (q1 >= 4.0f) + (q2 >= 4.0f) + (q3 >= 4.0f);
}

__global__ __launch_bounds__(NT, 4)
void k_mmh(const float4* __restrict__ x, int n4,
           const float* __restrict__ xs, int n, int ntiles,
           const float* __restrict__ params,
           const float* __restrict__ ct_p,
           const float* __restrict__ st_p) {
    __shared__ float smn[NT / 32], smx[NT / 32];
    __shared__ float sAB[4];                 // A, B, dmin, width (broadcast)
    __shared__ unsigned int s_last;
    int w = threadIdx.x >> 5;
    int gtid = blockIdx.x * NT + threadIdx.x;

    // ---------- phase A: min/max, forward ----------
    float mn =  3.402823466e38f;
    float mx = -3.402823466e38f;
    int nt_b = 0;                            // tiles owned by this block
    for (int g = blockIdx.x; g < ntiles; g += GRID2) {
        int base = g * TILE2 + threadIdx.x;
        #pragma unroll
        for (int k = 0; k < UN2; k++) {
            float4 v = x[base + k * NT];
            mn = fminf(mn, fminf(fminf(v.x, v.y), fminf(v.z, v.w)));
            mx = fmaxf(mx, fmaxf(fmaxf(v.x, v.y), fmaxf(v.z, v.w)));
        }
        nt_b++;
    }
    for (int j = ntiles * TILE2 + gtid; j < n4; j += GRID2 * NT) {
        float4 v = x[j];
        mn = fminf(mn, fminf(fminf(v.x, v.y), fminf(v.z, v.w)));
        mx = fmaxf(mx, fmaxf(fmaxf(v.x, v.y), fmaxf(v.z, v.w)));
    }
    for (int j = (n4 << 2) + gtid; j < n; j += GRID2 * NT) {
        float v = xs[j];
        mn = fminf(mn, v); mx = fmaxf(mx, v);
    }
    #pragma unroll
    for (int o = 16; o > 0; o >>= 1) {
        mn = fminf(mn, __shfl_xor_sync(0xffffffffu, mn, o));
        mx = fmaxf(mx, __shfl_xor_sync(0xffffffffu, mx, o));
    }
    if ((threadIdx.x & 31) == 0) { smn[w] = mn; smx[w] = mx; }
    __syncthreads();

    // ---------- grid barrier (all 592 blocks resident by launch_bounds) ----------
    if (threadIdx.x == 0) {
        float bmn = smn[0], bmx = smx[0];
        #pragma unroll
        for (int k = 1; k < NT / 32; k++) { bmn = fminf(bmn, smn[k]); bmx = fmaxf(bmx, smx[k]); }
        g_pmin[blockIdx.x] = bmn;
        g_pmax[blockIdx.x] = bmx;
        __threadfence();
        atomicAdd((unsigned int*)&g_bar, 1u);
        while (g_bar < GRID2) __nanosleep(64);
    }
    __syncthreads();
    __threadfence();

    // ---------- every block reduces partials (identical result, no 2nd barrier) ----------
    {
        float rmn =  3.402823466e38f;
        float rmx = -3.402823466e38f;
        for (int i = threadIdx.x; i < GRID2; i += NT) {
            rmn = fminf(rmn, g_pmin[i]);
            rmx = fmaxf(rmx, g_pmax[i]);
        }
        #pragma unroll
        for (int o = 16; o > 0; o >>= 1) {
            rmn = fminf(rmn, __shfl_xor_sync(0xffffffffu, rmn, o));
            rmx = fmaxf(rmx, __shfl_xor_sync(0xffffffffu, rmx, o));
        }
        if ((threadIdx.x & 31) == 0) { smn[w] = rmn; smx[w] = rmx; }
        __syncthreads();
        if (threadIdx.x == 0) {
            #pragma unroll
            for (int k = 1; k < NT / 32; k++) { rmn = fminf(rmn, smn[k]); rmx = fmaxf(rmx, smx[k]); }
            float ct = ct_p[0];
            float a = ct * rmn, b = ct * rmx;       // monotone map, handles ct<0
            float dmn = fminf(a, b) - 0.1f;
            float dmx = fmaxf(a, b) + 0.1f;
            float wd = (dmx - dmn) / (float)NBINS;
            float invw = 1.0f / wd;
            sAB[0] = ct * invw;
            sAB[1] = -dmn * invw;
            sAB[2] = dmn;
            sAB[3] = wd;
        }
        __syncthreads();
    }
    const float A = sAB[0], B = sAB[1];

    // ---------- phase B: histogram, OWN tiles in REVERSE (L1/L2 hot) ----------
    unsigned int s1 = 0, s2 = 0, s3 = 0, s4 = 0;
    for (int i = nt_b - 1; i >= 0; i--) {
        int g = blockIdx.x + i * GRID2;
        int base = g * TILE2 + threadIdx.x;
        #pragma unroll
        for (int k = 0; k < UN2; k++)
            hist4(x[base + k * NT], A, B, s1, s2, s3, s4);
    }
    for (int j = ntiles * TILE2 + gtid; j < n4; j += GRID2 * NT)
        hist4(x[j], A, B, s1, s2, s3, s4);
    for (int j = (n4 << 2) + gtid; j < n; j += GRID2 * NT) {
        float q = fmaf(xs[j], A, B);
        s1 += (q >= 1.0f); s2 += (q >= 2.0f); s3 += (q >= 3.0f); s4 += (q >= 4.0f);
    }
    s1 = __reduce_add_sync(0xffffffffu, s1);
    s2 = __reduce_add_sync(0xffffffffu, s2);
    s3 = __reduce_add_sync(0xffffffffu, s3);
    s4 = __reduce_add_sync(0xffffffffu, s4);
    __shared__ unsigned int sc[4];
    if (threadIdx.x < 4) sc[threadIdx.x] = 0u;
    __syncthreads();
    if ((threadIdx.x & 31) == 0) {
        atomicAdd(&sc[0], s1); atomicAdd(&sc[1], s2);
        atomicAdd(&sc[2], s3); atomicAdd(&sc[3], s4);
    }
    __syncthreads();
    if (threadIdx.x == 0) {
        g_ps[blockIdx.x] = make_uint4(sc[0], sc[1], sc[2], sc[3]);
        __threadfence();
        unsigned int o = atomicAdd(&g_tk, 1u);
        s_last = (o == GRID2 - 1) ? 1u : 0u;
    }
    __syncthreads();
    if (!s_last) return;

    // ---------- last block: reduce hist partials + build tables ----------
    __threadfence();
    __shared__ float s_in[12];   // [0..9]=params, [10]=ct, [11]=st
    if (threadIdx.x < 10) s_in[threadIdx.x] = params[threadIdx.x];
    else if (threadIdx.x == 10) s_in[10] = ct_p[0];
    else if (threadIdx.x == 11) s_in[11] = st_p[0];

    unsigned int a1 = 0, a2 = 0, a3 = 0, a4 = 0;
    for (int i = threadIdx.x; i < GRID2; i += NT) {
        uint4 p = g_ps[i];
        a1 += p.x; a2 += p.y; a3 += p.z; a4 += p.w;
    }
    a1 = __reduce_add_sync(0xffffffffu, a1);
    a2 = __reduce_add_sync(0xffffffffu, a2);
    a3 = __reduce_add_sync(0xffffffffu, a3);
    a4 = __reduce_add_sync(0xffffffffu, a4);
    __shared__ unsigned int sr[4][NT / 32];
    if ((threadIdx.x & 31) == 0) { sr[0][w] = a1; sr[1][w] = a2; sr[2][w] = a3; sr[3][w] = a4; }
    __syncthreads();
    if (threadIdx.x != 0) return;
    #pragma unroll
    for (int k = 1; k < NT / 32; k++) { a1 += sr[0][k]; a2 += sr[1][k]; a3 += sr[2][k]; a4 += sr[3][k]; }

    const float dmin = sAB[2], wdt = sAB[3];
    const float ct = s_in[10], st = s_in[11];

    unsigned long long cnt[NBINS];
    cnt[0] = (unsigned long long)n - a1;
    cnt[1] = a1 - a2; cnt[2] = a2 - a3; cnt[3] = a3 - a4; cnt[4] = a4;

    // emulate fp32 +=1.0 accumulation: saturates exactly at 2^24
    float cf[NBINS];
    #pragma unroll
    for (int i = 0; i < NBINS; i++) {
        unsigned long long c = cnt[i];
        if (c > 16777216ull) c = 16777216ull;
        cf[i] = (float)c;
    }
    float s = cf[0] + cf[1] + cf[2] + cf[3] + cf[4];       // left-to-right fp32
    float accum[NBINS];
    float run = 0.0f;
    #pragma unroll
    for (int i = 0; i < NBINS; i++) {
        float prob = cf[i] / s;
        run += prob;
        accum[i] = run * (float)NBINS;
    }
    float edges[NBINS + 1], grid[NBINS];
    #pragma unroll
    for (int i = 0; i <= NBINS; i++) edges[i] = dmin + wdt * (float)i;
    #pragma unroll
    for (int i = 0; i < NBINS; i++) grid[i] = 0.5f * (edges[i + 1] + edges[i]);

    // per-segment (slope*ct, base) for index(x) = interp1d(grid, accum, x*ct)
    #pragma unroll
    for (int i = 0; i < NBINS - 1; i++) {
        float den = grid[i + 1] - grid[i];
        if (den == 0.0f) den = 1.0f;
        float slope = (accum[i + 1] - accum[i]) / den;
        g_tbl[2 * i]     = slope * ct;
        g_tbl[2 * i + 1] = accum[i] - slope * grid[i];
    }
    // frame = interp1d(accum, grid, arange(P))
    float frame[NBINS];
    #pragma unroll
    for (int q = 0; q < NBINS; q++) {
        float xq = (float)q;
        int ss = 0;
        #pragma unroll
        for (int j = 0; j < NBINS; j++) ss += (accum[j] < xq);
        int idx = min(max(ss - 1, 0), NBINS - 2);
        float den = accum[idx + 1] - accum[idx];
        if (den == 0.0f) den = 1.0f;
        frame[q] = grid[idx] + (grid[idx + 1] - grid[idx]) / den * (xq - accum[idx]);
    }
    float thp[NBINS], vep[NBINS];
    #pragma unroll
    for (int q = 0; q < NBINS; q++) {
        thp[q] = frame[q] + 0.001f * s_in[q];
        vep[q] = frame[q] + 0.001f * s_in[NBINS + q];
    }
    // 6 segments of (slope, intercept) in `index`, key = clamp(floor(index)+1, 0, 5)
    #pragma unroll
    for (int k = 0; k < 6; k++) {
        float tS, tI, vS, vI;
        if (k == 0)      { tS = 0.0f; tI = thp[0]; vS = 0.0f; vI = vep[0]; }
        else if (k == 5) { tS = 0.0f; tI = thp[4]; vS = 0.0f; vI = vep[4]; }
        else {
            int bi = k - 1;
            tS = thp[bi + 1] - thp[bi]; tI = thp[bi] - tS * (float)bi;
            vS = vep[bi + 1] - vep[bi]; vI = vep[bi] - vS * (float)bi;
        }
        g_tbl[8 + 4 * k + 0] = tS;
        g_tbl[8 + 4 * k + 1] = tI;
        g_tbl[8 + 4 * k + 2] = vS;
        g_tbl[8 + 4 * k + 3] = vI;
    }
    float invw = 1.0f / wdt;
    g_tbl[32] = ct * invw;
    g_tbl[33] = -dmin * invw - 0.5f;
    g_tbl[34] = st * ct;
    g_tbl[35] = st;
    // reset sync state for next graph replay (all blocks past barrier by now)
    g_bar = 0u;
    __threadfence();
    atomicExch(&g_tk, 0u);
}

// ---------------- kernel 2: elementwise apply (forward, streaming) ----------------
__device__ __forceinline__ float apply_one(float xv, const float2* sb, const float4* cf,
                                           float At, float c0, float stct, float st) {
    float t = fmaf(xv, At, c0);
    int idx = min(max(__float2int_rd(t), 0), NBINS - 2);
    float2 sp = sb[idx];
    float index = fmaf(xv, sp.x, sp.y);
    int k = min(max(__float2int_rd(index) + 1, 0), 5);
    float4 c = cf[k];
    float th = fmaf(index, c.x, c.y);
    float ve = fmaf(index, c.z, c.w);
    float sn, cs;
    __sincosf(th, &sn, &cs);
    return fmaf(xv, stct * fmaf(ve, sn, 1.0f), st * (ve * cs));
}

__global__ void k_apply(const float4* __restrict__ x, float4* __restrict__ o, int n4,
                        const float* __restrict__ xs, float* __restrict__ os, int n, int ntiles) {
    __shared__ __align__(16) float tbl[36];
    if (threadIdx.x < 36) tbl[threadIdx.x] = g_tbl[threadIdx.x];
    __syncthreads();
    const float2* sb = (const float2*)tbl;          // 4 pairs
    const float4* cf = (const float4*)(tbl + 8);    // 6 quads
    const float At = tbl[32], c0 = tbl[33], stct = tbl[34], st = tbl[35];
    for (int g = blockIdx.x; g < ntiles; g += GRIDA) {
        int base = g * TILE + threadIdx.x;
        float4 v0 = __ldcs(&x[base]);
        float4 v1 = __ldcs(&x[base + NT]);
        float4 v2 = __ldcs(&x[base + 2 * NT]);
        float4 v3 = __ldcs(&x[base + 3 * NT]);
        float4 r0, r1, r2, r3;
        r0.x = apply_one(v0.x, sb, cf, At, c0, stct, st);
        r0.y = apply_one(v0.y, sb, cf, At, c0, stct, st);
        r0.z = apply_one(v0.z, sb, cf, At, c0, stct, st);
        r0.w = apply_one(v0.w, sb, cf, At, c0, stct, st);
        r1.x = apply_one(v1.x, sb, cf, At, c0, stct, st);
        r1.y = apply_one(v1.y, sb, cf, At, c0, stct, st);
        r1.z = apply_one(v1.z, sb, cf, At, c0, stct, st);
        r1.w = apply_one(v1.w, sb, cf, At, c0, stct, st);
        r2.x = apply_one(v2.x, sb, cf, At, c0, stct, st);
        r2.y = apply_one(v2.y, sb, cf, At, c0, stct, st);
        r2.z = apply_one(v2.z, sb, cf, At, c0, stct, st);
        r2.w = apply_one(v2.w, sb, cf, At, c0, stct, st);
        r3.x = apply_one(v3.x, sb, cf, At, c0, stct, st);
        r3.y = apply_one(v3.y, sb, cf, At, c0, stct, st);
        r3.z = apply_one(v3.z, sb, cf, At, c0, stct, st);
        r3.w = apply_one(v3.w, sb, cf, At, c0, stct, st);
        __stcs(&o[base], r0);
        __stcs(&o[base + NT], r1);
        __stcs(&o[base + 2 * NT], r2);
        __stcs(&o[base + 3 * NT], r3);
    }
    int gtid = blockIdx.x * NT + threadIdx.x;
    for (int j = ntiles * TILE + gtid; j < n4; j += GRIDA * NT) {
        float4 v = __ldcs(&x[j]);
        float4 r;
        r.x = apply_one(v.x, sb, cf, At, c0, stct, st);
        r.y = apply_one(v.y, sb, cf, At, c0, stct, st);
        r.z = apply_one(v.z, sb, cf, At, c0, stct, st);
        r.w = apply_one(v.w, sb, cf, At, c0, stct, st);
        __stcs(&o[j], r);
    }
    for (int j = (n4 << 2) + gtid; j < n; j += GRIDA * NT)
        os[j] = apply_one(xs[j], sb, cf, At, c0, stct, st);
}

// ---------------- launch ----------------
extern "C" void kernel_launch(void* const* d_in, const int* in_sizes, int n_in,
                              void* d_out, int out_size) {
    const float* data   = (const float*)d_in[0];
    const float* params = (const float*)d_in[1];
    const float* ct     = (const float*)d_in[2];
    const float* st     = (const float*)d_in[3];
    float* out = (float*)d_out;
    int n       = in_sizes[0];
    int n4      = n >> 2;
    int ntiles2 = n4 / TILE2;
    int ntiles  = n4 / TILE;

    k_mmh<<<GRID2, NT>>>((const float4*)data, n4, data, n, ntiles2, params, ct, st);
    k_apply<<<GRIDA, NT>>>((const float4*)data, (float4*)out, n4, data, out, n, ntiles);
}